// round 3
// baseline (speedup 1.0000x reference)
#include <cuda_runtime.h>
#include <math.h>

#define NN 4096
#define DD 128
#define HH 4
#define NMID 9

// Scratch (device globals: no allocation allowed). 16B-aligned for float4 access.
__device__ __align__(16) float g_X0[NN * 512];
__device__ __align__(16) float g_X1[NN * 512];
__device__ __align__(16) float g_Wh[HH * NN * DD];
__device__ float g_f1[HH * NN];
__device__ float g_f2[HH * NN];
__device__ float g_m[HH * NN];
__device__ float g_si[HH * NN];
__device__ unsigned g_mask[NN * 128];  // 4096 bits per row = 128 words

// ---------------------------------------------------------------------------
// adj > 0 -> bitmask (2MB, lives in L2 for the whole pipeline)
// ---------------------------------------------------------------------------
__global__ void build_mask_kernel(const float* __restrict__ adj,
                                  unsigned* __restrict__ mask) {
    int i = blockIdx.x;
    int t = threadIdx.x;
    int lane = t & 31;
    const float* row = adj + (size_t)i * NN;
    for (int word = t >> 5; word < 128; word += 8) {
        float v = row[word * 32 + lane];
        unsigned b = __ballot_sync(0xffffffffu, v > 0.f);
        if (lane == 0) mask[i * 128 + word] = b;
    }
}

// ---------------------------------------------------------------------------
// head_relation_combined = entity_emb[head] + relation_emb[relation]
// ---------------------------------------------------------------------------
__global__ void hrc_kernel(const int* __restrict__ head, const int* __restrict__ rel,
                           const float* __restrict__ ee, const float* __restrict__ re,
                           float* __restrict__ out) {
    int i = blockIdx.x;
    int d = threadIdx.x;
    out[(size_t)i * 128 + d] =
        ee[(size_t)head[i] * 128 + d] + re[(size_t)rel[i] * 128 + d];
}

// ---------------------------------------------------------------------------
// Wh[h] = X @ W[h]   (M=4096, N=128, K=Fin), block tile 64x128, 256 threads
// ---------------------------------------------------------------------------
__global__ void gemm_xw_kernel(const float* __restrict__ X, const float* __restrict__ W,
                               float* __restrict__ Wh, int Fin) {
    int h = blockIdx.z;
    int row0 = blockIdx.x * 64;
    const float* Wp = W + (size_t)h * Fin * 128;
    float* outp = Wh + (size_t)h * NN * 128;

    __shared__ float Xs[64][32];
    __shared__ float Ws[32][128];

    int t = threadIdx.x;
    int tx = t & 31, ty = t >> 5;
    float acc[8][4] = {};

    for (int k0 = 0; k0 < Fin; k0 += 32) {
        __syncthreads();
        // Xs: 64x32 floats = 512 float4
#pragma unroll
        for (int l = 0; l < 2; l++) {
            int idx = t + l * 256;
            int r = idx >> 3;     // 8 float4 per 32-float row
            int c4 = idx & 7;
            *(float4*)&Xs[r][c4 * 4] =
                *(const float4*)&X[(size_t)(row0 + r) * Fin + k0 + c4 * 4];
        }
        // Ws: 32x128 floats = 1024 float4
#pragma unroll
        for (int l = 0; l < 4; l++) {
            int idx = t + l * 256;
            int r = idx >> 5;     // 32 float4 per 128-float row
            int c4 = idx & 31;
            *(float4*)&Ws[r][c4 * 4] =
                *(const float4*)&Wp[(size_t)(k0 + r) * 128 + c4 * 4];
        }
        __syncthreads();
#pragma unroll
        for (int k = 0; k < 32; k += 4) {
            float4 b0 = *(float4*)&Ws[k + 0][tx * 4];
            float4 b1 = *(float4*)&Ws[k + 1][tx * 4];
            float4 b2 = *(float4*)&Ws[k + 2][tx * 4];
            float4 b3 = *(float4*)&Ws[k + 3][tx * 4];
#pragma unroll
            for (int r = 0; r < 8; r++) {
                float4 a = *(float4*)&Xs[ty * 8 + r][k];
                acc[r][0] = fmaf(a.x, b0.x, acc[r][0]);
                acc[r][1] = fmaf(a.x, b0.y, acc[r][1]);
                acc[r][2] = fmaf(a.x, b0.z, acc[r][2]);
                acc[r][3] = fmaf(a.x, b0.w, acc[r][3]);
                acc[r][0] = fmaf(a.y, b1.x, acc[r][0]);
                acc[r][1] = fmaf(a.y, b1.y, acc[r][1]);
                acc[r][2] = fmaf(a.y, b1.z, acc[r][2]);
                acc[r][3] = fmaf(a.y, b1.w, acc[r][3]);
                acc[r][0] = fmaf(a.z, b2.x, acc[r][0]);
                acc[r][1] = fmaf(a.z, b2.y, acc[r][1]);
                acc[r][2] = fmaf(a.z, b2.z, acc[r][2]);
                acc[r][3] = fmaf(a.z, b2.w, acc[r][3]);
                acc[r][0] = fmaf(a.w, b3.x, acc[r][0]);
                acc[r][1] = fmaf(a.w, b3.y, acc[r][1]);
                acc[r][2] = fmaf(a.w, b3.z, acc[r][2]);
                acc[r][3] = fmaf(a.w, b3.w, acc[r][3]);
            }
        }
    }
#pragma unroll
    for (int r = 0; r < 8; r++) {
        int row = row0 + ty * 8 + r;
#pragma unroll
        for (int c = 0; c < 4; c++)
            outp[(size_t)row * 128 + tx * 4 + c] = acc[r][c];
    }
}

// ---------------------------------------------------------------------------
// f1[i] = Wh[i,:] . a[0:128];  f2[i] = Wh[i,:] . a[128:256]
// ---------------------------------------------------------------------------
__global__ void compute_f_kernel(const float* __restrict__ Wh, const float* __restrict__ A,
                                 float* __restrict__ f1, float* __restrict__ f2) {
    int h = blockIdx.y;
    int warp = threadIdx.x >> 5, lane = threadIdx.x & 31;
    int i = blockIdx.x * 8 + warp;
    const float* row = Wh + ((size_t)h * NN + i) * 128;
    const float* a = A + h * 256;
    float s1 = 0.f, s2 = 0.f;
#pragma unroll
    for (int d = lane; d < 128; d += 32) {
        float v = row[d];
        s1 += v * a[d];
        s2 += v * a[128 + d];
    }
#pragma unroll
    for (int o = 16; o; o >>= 1) {
        s1 += __shfl_xor_sync(0xffffffffu, s1, o);
        s2 += __shfl_xor_sync(0xffffffffu, s2, o);
    }
    if (lane == 0) {
        f1[h * NN + i] = s1;
        f2[h * NN + i] = s2;
    }
}

// ---------------------------------------------------------------------------
// Per-row softmax stats: m = max_j(masked e_ij), si = 1/sum exp(e-m)
// ---------------------------------------------------------------------------
__global__ void stats_kernel(const float* __restrict__ f1, const float* __restrict__ f2,
                             const unsigned* __restrict__ mask,
                             float* __restrict__ mo, float* __restrict__ sio) {
    int h = blockIdx.y;
    int rowbase = blockIdx.x * 16;
    __shared__ float f2s[NN];
    __shared__ unsigned mws[16][128];
    int t = threadIdx.x;
    for (int j = t; j < NN; j += 256) f2s[j] = f2[h * NN + j];
    for (int idx = t; idx < 16 * 128; idx += 256) {
        int r = idx >> 7, w = idx & 127;
        mws[r][w] = mask[(size_t)(rowbase + r) * 128 + w];
    }
    __syncthreads();
    int warp = t >> 5, lane = t & 31;
    for (int rr = warp; rr < 16; rr += 8) {
        int i = rowbase + rr;
        float fr = f1[h * NN + i];
        float mmax = -1e30f;
        for (int w = 0; w < 128; w++) {
            unsigned msk = mws[rr][w];
            if ((msk >> lane) & 1u) {
                float e = fr + f2s[w * 32 + lane];
                e = e > 0.f ? e : 0.2f * e;
                mmax = fmaxf(mmax, e);
            }
        }
#pragma unroll
        for (int o = 16; o; o >>= 1)
            mmax = fmaxf(mmax, __shfl_xor_sync(0xffffffffu, mmax, o));
        float s = 0.f;
        for (int w = 0; w < 128; w++) {
            unsigned msk = mws[rr][w];
            if ((msk >> lane) & 1u) {
                float e = fr + f2s[w * 32 + lane];
                e = e > 0.f ? e : 0.2f * e;
                s += __expf(e - mmax);
            }
        }
#pragma unroll
        for (int o = 16; o; o >>= 1) s += __shfl_xor_sync(0xffffffffu, s, o);
        if (lane == 0) {
            mo[h * NN + i] = mmax;
            sio[h * NN + i] = 1.f / s;
        }
    }
}

// ---------------------------------------------------------------------------
// out_tile[64x128] = softmax_row(e) @ Wh, p generated on the fly (rank-1 + mask),
// elu epilogue, written at column offset h*128 with given row stride.
// ---------------------------------------------------------------------------
__global__ void attn_kernel(const float* __restrict__ Wh, const float* __restrict__ f1,
                            const float* __restrict__ f2, const float* __restrict__ mvec,
                            const float* __restrict__ sivec, const unsigned* __restrict__ mask,
                            float* __restrict__ out, int out_stride) {
    int h = blockIdx.z;
    int row0 = blockIdx.x * 64;
    const float* Whh = Wh + (size_t)h * NN * 128;

    __shared__ float Whs[32][128];
    __shared__ float Ps[64][32];
    __shared__ float f1s[64], ms[64], sis[64];
    __shared__ unsigned mw[64];
    __shared__ float f2s[32];

    int t = threadIdx.x, tx = t & 31, ty = t >> 5;
    if (t < 64) {
        f1s[t] = f1[h * NN + row0 + t];
        ms[t] = mvec[h * NN + row0 + t];
        sis[t] = sivec[h * NN + row0 + t];
    }
    float acc[8][4] = {};

    for (int k0 = 0; k0 < NN; k0 += 32) {
        __syncthreads();  // protect Whs/Ps/f2s/mw from previous iter's readers
        // Whs: 32x128 floats = 1024 float4
#pragma unroll
        for (int l = 0; l < 4; l++) {
            int idx = t + l * 256;
            int r = idx >> 5, c4 = idx & 31;
            *(float4*)&Whs[r][c4 * 4] =
                *(const float4*)&Whh[(size_t)(k0 + r) * 128 + c4 * 4];
        }
        if (t < 32) f2s[t] = f2[h * NN + k0 + t];
        if (t < 64) mw[t] = mask[(size_t)(row0 + t) * 128 + (k0 >> 5)];
        __syncthreads();
        // generate P tile: lane tx = column, rows ty + 8e
        {
            float f2v = f2s[tx];
#pragma unroll
            for (int e8 = 0; e8 < 8; e8++) {
                int r = ty + 8 * e8;
                unsigned w = mw[r];
                float ev = f1s[r] + f2v;
                ev = ev > 0.f ? ev : 0.2f * ev;
                float p = ((w >> tx) & 1u) ? __expf(ev - ms[r]) * sis[r] : 0.f;
                Ps[r][tx] = p;
            }
        }
        __syncthreads();  // P written column-per-thread, read row-per-thread
#pragma unroll
        for (int k = 0; k < 32; k += 4) {
            float4 b0 = *(float4*)&Whs[k + 0][tx * 4];
            float4 b1 = *(float4*)&Whs[k + 1][tx * 4];
            float4 b2 = *(float4*)&Whs[k + 2][tx * 4];
            float4 b3 = *(float4*)&Whs[k + 3][tx * 4];
#pragma unroll
            for (int r = 0; r < 8; r++) {
                float4 p4 = *(float4*)&Ps[ty * 8 + r][k];
                acc[r][0] = fmaf(p4.x, b0.x, acc[r][0]);
                acc[r][1] = fmaf(p4.x, b0.y, acc[r][1]);
                acc[r][2] = fmaf(p4.x, b0.z, acc[r][2]);
                acc[r][3] = fmaf(p4.x, b0.w, acc[r][3]);
                acc[r][0] = fmaf(p4.y, b1.x, acc[r][0]);
                acc[r][1] = fmaf(p4.y, b1.y, acc[r][1]);
                acc[r][2] = fmaf(p4.y, b1.z, acc[r][2]);
                acc[r][3] = fmaf(p4.y, b1.w, acc[r][3]);
                acc[r][0] = fmaf(p4.z, b2.x, acc[r][0]);
                acc[r][1] = fmaf(p4.z, b2.y, acc[r][1]);
                acc[r][2] = fmaf(p4.z, b2.z, acc[r][2]);
                acc[r][3] = fmaf(p4.z, b2.w, acc[r][3]);
                acc[r][0] = fmaf(p4.w, b3.x, acc[r][0]);
                acc[r][1] = fmaf(p4.w, b3.y, acc[r][1]);
                acc[r][2] = fmaf(p4.w, b3.z, acc[r][2]);
                acc[r][3] = fmaf(p4.w, b3.w, acc[r][3]);
            }
        }
    }
    // elu epilogue + concat write
#pragma unroll
    for (int r = 0; r < 8; r++) {
        int row = row0 + ty * 8 + r;
#pragma unroll
        for (int c = 0; c < 4; c++) {
            float v = acc[r][c];
            v = v > 0.f ? v : expm1f(v);
            out[(size_t)row * out_stride + h * 128 + tx * 4 + c] = v;
        }
    }
}

// ---------------------------------------------------------------------------
extern "C" void kernel_launch(void* const* d_in, const int* in_sizes, int n_in,
                              void* d_out, int out_size) {
    const int* head = (const int*)d_in[0];
    const int* rel = (const int*)d_in[1];
    const float* adj = (const float*)d_in[2];
    const float* ee = (const float*)d_in[3];
    const float* re = (const float*)d_in[4];
    const float* W0 = (const float*)d_in[5];
    const float* a0 = (const float*)d_in[6];
    const float* Wm = (const float*)d_in[7];
    const float* am = (const float*)d_in[8];
    const float* Wo = (const float*)d_in[9];
    const float* ao = (const float*)d_in[10];
    float* out = (float*)d_out;

    float *X0, *X1, *Wh, *f1, *f2, *mv, *si;
    unsigned* mask;
    cudaGetSymbolAddress((void**)&X0, g_X0);
    cudaGetSymbolAddress((void**)&X1, g_X1);
    cudaGetSymbolAddress((void**)&Wh, g_Wh);
    cudaGetSymbolAddress((void**)&f1, g_f1);
    cudaGetSymbolAddress((void**)&f2, g_f2);
    cudaGetSymbolAddress((void**)&mv, g_m);
    cudaGetSymbolAddress((void**)&si, g_si);
    cudaGetSymbolAddress((void**)&mask, g_mask);

    build_mask_kernel<<<NN, 256>>>(adj, mask);
    hrc_kernel<<<NN, 128>>>(head, rel, ee, re, out + (size_t)NN * 128);

    // layer 0: D -> H*D
    gemm_xw_kernel<<<dim3(64, 1, HH), 256>>>(ee, W0, Wh, 128);
    compute_f_kernel<<<dim3(512, HH), 256>>>(Wh, a0, f1, f2);
    stats_kernel<<<dim3(256, HH), 256>>>(f1, f2, mask, mv, si);
    attn_kernel<<<dim3(64, 1, HH), 256>>>(Wh, f1, f2, mv, si, mask, X0, 512);

    // 9 middle layers: H*D -> H*D (ping-pong X0/X1)
    float* cur = X0;
    float* nxt = X1;
    for (int l = 0; l < NMID; l++) {
        gemm_xw_kernel<<<dim3(64, 1, HH), 256>>>(cur, Wm + (size_t)l * HH * 512 * 128, Wh, 512);
        compute_f_kernel<<<dim3(512, HH), 256>>>(Wh, am + (size_t)l * HH * 256, f1, f2);
        stats_kernel<<<dim3(256, HH), 256>>>(f1, f2, mask, mv, si);
        attn_kernel<<<dim3(64, 1, HH), 256>>>(Wh, f1, f2, mv, si, mask, nxt, 512);
        float* tmp = cur; cur = nxt; nxt = tmp;
    }

    // output layer: single head H*D -> D, elu, write to d_out[0 : 4096*128]
    gemm_xw_kernel<<<dim3(64, 1, 1), 256>>>(cur, Wo, Wh, 512);
    compute_f_kernel<<<dim3(512, 1), 256>>>(Wh, ao, f1, f2);
    stats_kernel<<<dim3(256, 1), 256>>>(f1, f2, mask, mv, si);
    attn_kernel<<<dim3(64, 1, 1), 256>>>(Wh, f1, f2, mv, si, mask, out, 128);
}